// round 2
// baseline (speedup 1.0000x reference)
#include <cuda_runtime.h>
#include <math.h>

// Problem dimensions (fixed by setup_inputs)
#define Nn 50000
#define Ee 400000
#define Rr 8

// Scratch (device globals — no allocation allowed)
__device__ float g_cnt[Nn * Rr];                    // becomes 1/max(cnt,1)
__device__ float g_agg[(size_t)Nn * Rr * 256];      // per-(node,rel) aggregate, reused both layers
__device__ float g_h1[(size_t)Nn * 256];
__device__ float g_h2[(size_t)Nn * 128];
__device__ float g_Pa[(size_t)Nn * 256];            // h2 @ Wm1[0:128]   + bm1
__device__ float g_Pb[(size_t)Nn * 256];            // h2 @ Wm1[128:256]

// ---------------------------------------------------------------------------
__global__ void k_zero4(float4* __restrict__ p, size_t n4) {
    size_t i = (size_t)blockIdx.x * blockDim.x + threadIdx.x;
    size_t stride = (size_t)gridDim.x * blockDim.x;
    float4 z = make_float4(0.f, 0.f, 0.f, 0.f);
    for (; i < n4; i += stride) p[i] = z;
}

__global__ void k_mask_init(float* __restrict__ mask, int E) {
    int i = blockIdx.x * blockDim.x + threadIdx.x;
    if (i < E) mask[i] = 1.0f;
}

// last-occurrence-wins scatter of sigmoid(m_logits) (deterministic under dup indices)
__global__ void k_mask_scatter(const int* __restrict__ sub, const float* __restrict__ ml,
                               float* __restrict__ mask, int S) {
    int i = blockIdx.x * blockDim.x + threadIdx.x;
    if (i >= S) return;
    int idx = sub[i];
    for (int j = i + 1; j < S; j++)
        if (sub[j] == idx) return;
    mask[idx] = 1.0f / (1.0f + expf(-ml[i]));
}

__global__ void k_count(const int* __restrict__ dst, const int* __restrict__ et,
                        float* __restrict__ cnt, int E) {
    int e = blockIdx.x * blockDim.x + threadIdx.x;
    if (e < E) atomicAdd(&cnt[dst[e] * Rr + et[e]], 1.0f);
}

__global__ void k_invcnt(float* __restrict__ cnt, int n) {
    int i = blockIdx.x * blockDim.x + threadIdx.x;
    if (i < n) cnt[i] = 1.0f / fmaxf(cnt[i], 1.0f);
}

// 64 threads per edge; each handles 4 dims (float4 read, 4 scalar red.add)
__global__ void k_agg(const float* __restrict__ x, const int* __restrict__ src,
                      const int* __restrict__ dst, const int* __restrict__ et,
                      float* __restrict__ agg, int E) {
    int idx = blockIdx.x * blockDim.x + threadIdx.x;
    int e = idx >> 6;
    int lane = idx & 63;
    if (e >= E) return;
    int s = src[e];
    size_t base = ((size_t)dst[e] * Rr + et[e]) * 256 + lane * 4;
    float4 v = *(const float4*)(x + (size_t)s * 256 + lane * 4);
    atomicAdd(&agg[base + 0], v.x);
    atomicAdd(&agg[base + 1], v.y);
    atomicAdd(&agg[base + 2], v.z);
    atomicAdd(&agg[base + 3], v.w);
}

// ---------------------------------------------------------------------------
// 128x128x16 fp32 SGEMM, 256 threads, 8x8 per thread (4+4 split fragments).
// RGCN mode: A is the virtual [M, 2304] = [x | agg_r * inv_r] matrix (on-the-fly),
//            B is the virtual [2304, Nc] = [root ; W] matrix (two pointers).
template <bool RGCN, bool RELU, bool BIAS>
__global__ __launch_bounds__(256)
void k_sgemm(int M, int K, int Nc,
             const float* __restrict__ A0, int lda,
             const float* __restrict__ B0, const float* __restrict__ B1, int ldb,
             const float* __restrict__ bias,
             float* __restrict__ C, int ldc) {
    __shared__ float As[16][128];
    __shared__ float Bs[16][128];
    int tid = threadIdx.x;
    int n0 = blockIdx.x * 128;
    int m0 = blockIdx.y * 128;
    int tx = tid & 15, ty = tid >> 4;

    float acc[8][8];
#pragma unroll
    for (int i = 0; i < 8; i++)
#pragma unroll
        for (int j = 0; j < 8; j++) acc[i][j] = 0.f;

    for (int k0 = 0; k0 < K; k0 += 16) {
        // --- A tile: 128 rows x 16 cols, stored transposed As[k][m] ---
#pragma unroll
        for (int l = 0; l < 2; l++) {
            int q = tid + l * 256;          // 512 float4 total
            int m = q >> 2;
            int c4 = (q & 3) * 4;
            int gm = m0 + m;
            int gk = k0 + c4;
            float4 v = make_float4(0.f, 0.f, 0.f, 0.f);
            if (gm < M) {
                if (RGCN) {
                    if (gk < 256) {
                        v = *(const float4*)(A0 + (size_t)gm * lda + gk);
                    } else {
                        int rr = (gk >> 8) - 1;
                        v = *(const float4*)(g_agg + ((size_t)gm * Rr + rr) * 256 + (gk & 255));
                        float s = g_cnt[gm * Rr + rr];
                        v.x *= s; v.y *= s; v.z *= s; v.w *= s;
                    }
                } else {
                    v = *(const float4*)(A0 + (size_t)gm * lda + gk);
                }
            }
            As[c4 + 0][m] = v.x;
            As[c4 + 1][m] = v.y;
            As[c4 + 2][m] = v.z;
            As[c4 + 3][m] = v.w;
        }
        // --- B tile: 16 rows x 128 cols ---
#pragma unroll
        for (int l = 0; l < 2; l++) {
            int q = tid + l * 256;
            int kb = q >> 5;
            int j = (q & 31) * 4;
            int gk = k0 + kb;
            const float* Brow;
            if (RGCN)
                Brow = (gk < 256) ? (B0 + (size_t)gk * ldb) : (B1 + (size_t)(gk - 256) * ldb);
            else
                Brow = B0 + (size_t)gk * ldb;
            *(float4*)&Bs[kb][j] = *(const float4*)(Brow + n0 + j);
        }
        __syncthreads();

#pragma unroll
        for (int kk = 0; kk < 16; kk++) {
            float a[8], b[8];
            *(float4*)(a)     = *(float4*)&As[kk][ty * 4];
            *(float4*)(a + 4) = *(float4*)&As[kk][ty * 4 + 64];
            *(float4*)(b)     = *(float4*)&Bs[kk][tx * 4];
            *(float4*)(b + 4) = *(float4*)&Bs[kk][tx * 4 + 64];
#pragma unroll
            for (int i = 0; i < 8; i++)
#pragma unroll
                for (int j = 0; j < 8; j++) acc[i][j] += a[i] * b[j];
        }
        __syncthreads();
    }

    // --- epilogue ---
    float4 bv0 = make_float4(0.f, 0.f, 0.f, 0.f), bv1 = bv0;
    if (BIAS) {
        bv0 = *(const float4*)(bias + n0 + tx * 4);
        bv1 = *(const float4*)(bias + n0 + tx * 4 + 64);
    }
#pragma unroll
    for (int i = 0; i < 8; i++) {
        int gm = m0 + ty * 4 + (i & 3) + ((i >> 2) << 6);
        if (gm >= M) continue;
        float4 v0, v1;
        v0.x = acc[i][0] + bv0.x; v0.y = acc[i][1] + bv0.y;
        v0.z = acc[i][2] + bv0.z; v0.w = acc[i][3] + bv0.w;
        v1.x = acc[i][4] + bv1.x; v1.y = acc[i][5] + bv1.y;
        v1.z = acc[i][6] + bv1.z; v1.w = acc[i][7] + bv1.w;
        if (RELU) {
            v0.x = fmaxf(v0.x, 0.f); v0.y = fmaxf(v0.y, 0.f);
            v0.z = fmaxf(v0.z, 0.f); v0.w = fmaxf(v0.w, 0.f);
            v1.x = fmaxf(v1.x, 0.f); v1.y = fmaxf(v1.y, 0.f);
            v1.z = fmaxf(v1.z, 0.f); v1.w = fmaxf(v1.w, 0.f);
        }
        *(float4*)(C + (size_t)gm * ldc + n0 + tx * 4)      = v0;
        *(float4*)(C + (size_t)gm * ldc + n0 + tx * 4 + 64) = v1;
    }
}

// ---------------------------------------------------------------------------
// Fused: Tx-tile GEMM (64 edges x 256 cols, K=256) + final edge MLP epilogue.
//   tx_ec = e_text[e] @ Wm1c[:,c]
//   logit[e] = sum_c relu(Pa[src[e]][c] + Pb[dst[e]][c] + mask[e]*tx_ec) * Wm2[c] + bm2
// 256 threads = 8 warps; warp w owns rows w*8..w*8+7 and ALL 256 cols
// (lane covers cols lane*4..lane*4+3 and 128+lane*4..+3) -> shfl reduction.
__global__ __launch_bounds__(256)
void k_text_final(const float* __restrict__ text, const float* __restrict__ Wc,
                  const float* __restrict__ Pa, const float* __restrict__ Pb,
                  const float* __restrict__ mask,
                  const int* __restrict__ src, const int* __restrict__ dst,
                  const float* __restrict__ Wm2, const float* __restrict__ bm2,
                  float* __restrict__ logits, int E) {
    __shared__ float As[16][64];     // A transposed: As[k][m]
    __shared__ float Bs[16][256];
    int tid = threadIdx.x;
    int lane = tid & 31;
    int wrp = tid >> 5;
    int m0 = blockIdx.x * 64;

    float acc[8][8];
#pragma unroll
    for (int i = 0; i < 8; i++)
#pragma unroll
        for (int j = 0; j < 8; j++) acc[i][j] = 0.f;

    for (int k0 = 0; k0 < 256; k0 += 16) {
        // A tile: 64 rows x 16 cols = 256 float4, one per thread
        {
            int m = tid >> 2;
            int c4 = (tid & 3) * 4;
            int gm = m0 + m;
            float4 v = make_float4(0.f, 0.f, 0.f, 0.f);
            if (gm < E) v = *(const float4*)(text + (size_t)gm * 256 + k0 + c4);
            As[c4 + 0][m] = v.x;
            As[c4 + 1][m] = v.y;
            As[c4 + 2][m] = v.z;
            As[c4 + 3][m] = v.w;
        }
        // B tile: 16 rows x 256 cols = 1024 float4, 4 per thread
#pragma unroll
        for (int l = 0; l < 4; l++) {
            int q = tid + l * 256;
            int kb = q >> 6;
            int j = (q & 63) * 4;
            *(float4*)&Bs[kb][j] = *(const float4*)(Wc + (size_t)(k0 + kb) * 256 + j);
        }
        __syncthreads();

#pragma unroll
        for (int kk = 0; kk < 16; kk++) {
            float a[8];
            *(float4*)(a)     = *(float4*)&As[kk][wrp * 8];
            *(float4*)(a + 4) = *(float4*)&As[kk][wrp * 8 + 4];
            float4 b0 = *(float4*)&Bs[kk][lane * 4];
            float4 b1 = *(float4*)&Bs[kk][128 + lane * 4];
#pragma unroll
            for (int i = 0; i < 8; i++) {
                acc[i][0] += a[i] * b0.x; acc[i][1] += a[i] * b0.y;
                acc[i][2] += a[i] * b0.z; acc[i][3] += a[i] * b0.w;
                acc[i][4] += a[i] * b1.x; acc[i][5] += a[i] * b1.y;
                acc[i][6] += a[i] * b1.z; acc[i][7] += a[i] * b1.w;
            }
        }
        __syncthreads();
    }

    // Epilogue: per edge (row), fuse Pa/Pb gather + relu + dot(Wm2) + reduce
    float4 w0 = *(const float4*)(Wm2 + lane * 4);
    float4 w1 = *(const float4*)(Wm2 + 128 + lane * 4);
    float bb = bm2[0];
#pragma unroll
    for (int i = 0; i < 8; i++) {
        int e = m0 + wrp * 8 + i;
        if (e >= E) continue;
        int s = src[e], d = dst[e];
        float mk = mask[e];
        float4 pa0 = *(const float4*)(Pa + (size_t)s * 256 + lane * 4);
        float4 pa1 = *(const float4*)(Pa + (size_t)s * 256 + 128 + lane * 4);
        float4 pb0 = *(const float4*)(Pb + (size_t)d * 256 + lane * 4);
        float4 pb1 = *(const float4*)(Pb + (size_t)d * 256 + 128 + lane * 4);
        float p = 0.f;
        p += fmaxf(pa0.x + pb0.x + mk * acc[i][0], 0.f) * w0.x;
        p += fmaxf(pa0.y + pb0.y + mk * acc[i][1], 0.f) * w0.y;
        p += fmaxf(pa0.z + pb0.z + mk * acc[i][2], 0.f) * w0.z;
        p += fmaxf(pa0.w + pb0.w + mk * acc[i][3], 0.f) * w0.w;
        p += fmaxf(pa1.x + pb1.x + mk * acc[i][4], 0.f) * w1.x;
        p += fmaxf(pa1.y + pb1.y + mk * acc[i][5], 0.f) * w1.y;
        p += fmaxf(pa1.z + pb1.z + mk * acc[i][6], 0.f) * w1.z;
        p += fmaxf(pa1.w + pb1.w + mk * acc[i][7], 0.f) * w1.w;
#pragma unroll
        for (int off = 16; off; off >>= 1) p += __shfl_down_sync(0xffffffffu, p, off);
        if (lane == 0) logits[e] = p + bb;
    }
}

// ---------------------------------------------------------------------------
extern "C" void kernel_launch(void* const* d_in, const int* in_sizes, int n_in,
                              void* d_out, int out_size) {
    const int*   edge_index = (const int*)d_in[0];
    const int*   edge_type  = (const int*)d_in[1];
    const float* e_text     = (const float*)d_in[2];
    const int*   sub_idx    = (const int*)d_in[3];
    const float* m_logits   = (const float*)d_in[4];
    const float* node_emb   = (const float*)d_in[5];
    const float* W1         = (const float*)d_in[6];
    const float* root1      = (const float*)d_in[7];
    const float* b1         = (const float*)d_in[8];
    const float* W2         = (const float*)d_in[9];
    const float* root2      = (const float*)d_in[10];
    const float* b2         = (const float*)d_in[11];
    const float* Wm1        = (const float*)d_in[12];
    const float* bm1        = (const float*)d_in[13];
    const float* Wm2        = (const float*)d_in[14];
    const float* bm2        = (const float*)d_in[15];

    int E = in_sizes[1];
    int S = in_sizes[3];
    int N = in_sizes[5] / 256;

    const int* src = edge_index;
    const int* dst = edge_index + E;
    float* logits = (float*)d_out;
    float* mask   = logits + E;

    float *agg, *cnt, *h1, *h2, *Pa, *Pb;
    cudaGetSymbolAddress((void**)&agg, g_agg);
    cudaGetSymbolAddress((void**)&cnt, g_cnt);
    cudaGetSymbolAddress((void**)&h1,  g_h1);
    cudaGetSymbolAddress((void**)&h2,  g_h2);
    cudaGetSymbolAddress((void**)&Pa,  g_Pa);
    cudaGetSymbolAddress((void**)&Pb,  g_Pb);

    // zero accumulation scratch
    k_zero4<<<4096, 256>>>((float4*)agg, ((size_t)N * Rr * 256) / 4);
    k_zero4<<<64, 256>>>((float4*)cnt, ((size_t)N * Rr) / 4);

    // edge mask -> out[E..2E)
    k_mask_init<<<(E + 255) / 256, 256>>>(mask, E);
    k_mask_scatter<<<(S + 255) / 256, 256>>>(sub_idx, m_logits, mask, S);

    // counts (shared by both layers), stored as reciprocals
    k_count<<<(E + 255) / 256, 256>>>(dst, edge_type, cnt, E);
    k_invcnt<<<(N * Rr + 255) / 256, 256>>>(cnt, N * Rr);

    // ---- layer 1: h1 = relu([x | agg/cnt] @ [root1 ; W1] + b1) ----
    k_agg<<<(E + 3) / 4, 256>>>(node_emb, src, dst, edge_type, agg, E);
    {
        dim3 g(256 / 128, (N + 127) / 128);
        k_sgemm<true, true, true><<<g, 256>>>(N, 2304, 256, node_emb, 256,
                                              root1, W1, 256, b1, h1, 256);
    }

    // ---- layer 2: h2 = relu([h1 | agg/cnt] @ [root2 ; W2] + b2) ----
    k_zero4<<<4096, 256>>>((float4*)agg, ((size_t)N * Rr * 256) / 4);
    k_agg<<<(E + 3) / 4, 256>>>(h1, src, dst, edge_type, agg, E);
    {
        dim3 g(128 / 128, (N + 127) / 128);
        k_sgemm<true, true, true><<<g, 256>>>(N, 2304, 128, h1, 256,
                                              root2, W2, 128, b2, h2, 128);
    }

    // ---- MLP factorization: Pa = h2@Wm1[0:128] + bm1 ; Pb = h2@Wm1[128:256] ----
    {
        dim3 g(256 / 128, (N + 127) / 128);
        k_sgemm<false, false, true><<<g, 256>>>(N, 128, 256, h2, 128,
                                                Wm1, nullptr, 256, bm1, Pa, 256);
        k_sgemm<false, false, false><<<g, 256>>>(N, 128, 256, h2, 128,
                                                 Wm1 + 128 * 256, nullptr, 256, nullptr, Pb, 256);
    }

    // ---- fused text GEMM + final per-edge logits ----
    k_text_final<<<(E + 63) / 64, 256>>>(e_text, Wm1 + 256 * 256, Pa, Pb, mask,
                                         src, dst, Wm2, bm2, logits, E);
}